// round 4
// baseline (speedup 1.0000x reference)
#include <cuda_runtime.h>
#include <cuda_bf16.h>
#include <cstdint>
#include <math.h>

#define SSQ  1024
#define DD   1024
#define HHN  16
#define DHD  64
#define BHN  64
#define MTOT 4096
#define ATT_SCALE 0.03125f

// ---------------- fp32 scratch ----------------
__device__ float g_t [(size_t)BHN * SSQ * SSQ];   // 256 MB
__device__ float g_ac[(size_t)BHN * SSQ * SSQ];   // 256 MB
__device__ float g_o [(size_t)MTOT * DD];         // 16 MB merged-head fp32

// ---------------- bf16 pool ----------------
#define NX   ((size_t)MTOT * DD)
#define NW   ((size_t)DD * DD)
#define NH   ((size_t)BHN * SSQ * DHD)
#define O_XH  ((size_t)0)
#define O_XL  (O_XH + NX)
#define O_WQH (O_XL + NX)
#define O_WQL (O_WQH + NW)
#define O_WKH (O_WQL + NW)
#define O_WKL (O_WKH + NW)
#define O_WVH (O_WKL + NW)
#define O_WVL (O_WVH + NW)
#define O_WCH (O_WVL + NW)
#define O_WCL (O_WCH + NW)
#define O_QUH (O_WCL + NW)
#define O_QUL (O_QUH + NH)
#define O_QVH (O_QUL + NH)
#define O_QVL (O_QVH + NH)
#define O_KHH (O_QVL + NH)
#define O_KHL (O_KHH + NH)
#define O_RHH (O_KHL + NH)
#define O_RHL (O_RHH + NH)
#define O_VWH (O_RHL + NH)
#define O_VWL (O_VWH + NH)
#define O_OBH (O_VWL + NH)
#define O_OBL (O_OBH + NX)
#define BF_TOTAL (O_OBL + NX)
__device__ __align__(16) __nv_bfloat16 g_bf[BF_TOTAL];

// ================= helpers =================
__device__ __forceinline__ uint32_t smem_u32(const void* p) {
    uint32_t a;
    asm("{ .reg .u64 t; cvta.to.shared.u64 t, %1; cvt.u32.u64 %0, t; }" : "=r"(a) : "l"(p));
    return a;
}
__device__ __forceinline__ void split2(float v, __nv_bfloat16& h, __nv_bfloat16& l) {
    h = __float2bfloat16(v);
    l = __float2bfloat16(v - __bfloat162float(h));
}
__device__ __forceinline__ void cp16(uint32_t dst, const void* src) {
    asm volatile("cp.async.cg.shared.global [%0], [%1], 16;" :: "r"(dst), "l"(src));
}
__device__ __forceinline__ void cp_commit() { asm volatile("cp.async.commit_group;"); }
__device__ __forceinline__ void ldsm4(uint32_t& r0, uint32_t& r1, uint32_t& r2, uint32_t& r3,
                                      uint32_t addr) {
    asm volatile("ldmatrix.sync.aligned.m8n8.x4.shared.b16 {%0,%1,%2,%3}, [%4];"
                 : "=r"(r0), "=r"(r1), "=r"(r2), "=r"(r3) : "r"(addr));
}
__device__ __forceinline__ void ldsm4t(uint32_t& r0, uint32_t& r1, uint32_t& r2, uint32_t& r3,
                                       uint32_t addr) {
    asm volatile("ldmatrix.sync.aligned.m8n8.x4.trans.shared.b16 {%0,%1,%2,%3}, [%4];"
                 : "=r"(r0), "=r"(r1), "=r"(r2), "=r"(r3) : "r"(addr));
}
__device__ __forceinline__ void mma_bf16(float* d, const uint32_t* a, const uint32_t* b) {
    asm volatile(
        "mma.sync.aligned.m16n8k16.row.col.f32.bf16.bf16.f32 "
        "{%0,%1,%2,%3}, {%4,%5,%6,%7}, {%8,%9}, {%0,%1,%2,%3};"
        : "+f"(d[0]), "+f"(d[1]), "+f"(d[2]), "+f"(d[3])
        : "r"(a[0]), "r"(a[1]), "r"(a[2]), "r"(a[3]), "r"(b[0]), "r"(b[1]));
}
// 16B-chunk XOR swizzle for 64B rows (GEMM stages)
__device__ __forceinline__ uint32_t swadr(uint32_t tb, int r, int c) {
    return tb + r * 64 + (((c ^ ((r >> 1) & 3))) << 4);
}

#define STAGE_SZ 32768
#define SMEM_BYTES (2 * STAGE_SZ)

__device__ __forceinline__ void stage_load(
    uint32_t sb, const __nv_bfloat16* Ah, const __nv_bfloat16* Al,
    const __nv_bfloat16* Bh, const __nv_bfloat16* Bl,
    int arow0, int brow0, int ldA, int ldB, int k0, int tid)
{
#pragma unroll
    for (int half = 0; half < 2; half++) {
        const int q = half * 256 + tid;
        const int r = q >> 2, c = q & 3;
        const int kel = k0 + c * 8;
        cp16(swadr(sb,          r, c), Ah + (size_t)(arow0 + r) * ldA + kel);
        cp16(swadr(sb +  8192,  r, c), Al + (size_t)(arow0 + r) * ldA + kel);
        cp16(swadr(sb + 16384,  r, c), Bh + (size_t)(brow0 + r) * ldB + kel);
        cp16(swadr(sb + 24576,  r, c), Bl + (size_t)(brow0 + r) * ldB + kel);
    }
}

__device__ __forceinline__ void compute_chunk(uint32_t sb, int wm, int wn, int lane,
                                              float acc[4][4][4])
{
    const uint32_t Ahb = sb, Alb = sb + 8192, Bhb = sb + 16384, Blb = sb + 24576;
#pragma unroll
    for (int kk = 0; kk < 2; kk++) {
        uint32_t ah[4][4], al[4][4], bh[4][2], bl[4][2];
        const int ar = wm * 64 + (lane & 15);
        const int ac = 2 * kk + (lane >> 4);
#pragma unroll
        for (int i = 0; i < 4; i++) {
            ldsm4(ah[i][0], ah[i][1], ah[i][2], ah[i][3], swadr(Ahb, ar + i * 16, ac));
            ldsm4(al[i][0], al[i][1], al[i][2], al[i][3], swadr(Alb, ar + i * 16, ac));
        }
        const int br = wn * 32 + (lane & 7) + ((lane >> 4) << 3);
        const int bc = 2 * kk + ((lane >> 3) & 1);
#pragma unroll
        for (int p = 0; p < 2; p++) {
            uint32_t t0, t1, t2, t3;
            ldsm4(t0, t1, t2, t3, swadr(Bhb, br + p * 16, bc));
            bh[2*p][0] = t0; bh[2*p][1] = t1; bh[2*p+1][0] = t2; bh[2*p+1][1] = t3;
            ldsm4(t0, t1, t2, t3, swadr(Blb, br + p * 16, bc));
            bl[2*p][0] = t0; bl[2*p][1] = t1; bl[2*p+1][0] = t2; bl[2*p+1][1] = t3;
        }
#pragma unroll
        for (int i = 0; i < 4; i++)
#pragma unroll
            for (int j = 0; j < 4; j++) {
                mma_bf16(acc[i][j], ah[i], bh[j]);
                mma_bf16(acc[i][j], ah[i], bl[j]);
                mma_bf16(acc[i][j], al[i], bh[j]);
            }
    }
}

// ================= conversion kernels =================
__global__ __launch_bounds__(256) void conv_split(
    const float* __restrict__ s, __nv_bfloat16* __restrict__ h,
    __nv_bfloat16* __restrict__ l, int n)
{
    int i = blockIdx.x * 256 + threadIdx.x;
    if (i < n) {
        __nv_bfloat16 hh, ll; split2(s[i], hh, ll);
        h[i] = hh; l[i] = ll;
    }
}

__global__ __launch_bounds__(256) void conv_pos(
    const float* __restrict__ pos, __nv_bfloat16* __restrict__ h,
    __nv_bfloat16* __restrict__ l)
{
    int d = blockIdx.x * 256 + threadIdx.x;
    int bh = d >> 16;
    int s  = (d >> 6) & 1023;
    int dd = d & 63;
    int b = bh >> 4, hh_ = bh & 15;
    float v = pos[(((size_t)b << 10) + s) * 1024 + (hh_ << 6) + dd];
    __nv_bfloat16 hb, lb; split2(v, hb, lb);
    h[d] = hb; l[d] = lb;
}

// ================= projection GEMM (mma.sync) =================
// mode 0: fp32 [m][n];  1: (c+u)->o1,(c+v)->o2 bf16 hi/lo head-major;
// mode 2: c->o1 bf16 hi/lo head-major
__global__ __launch_bounds__(256, 1) void mm_gemm(
    const __nv_bfloat16* __restrict__ Ah, const __nv_bfloat16* __restrict__ Al,
    const __nv_bfloat16* __restrict__ Bh, const __nv_bfloat16* __restrict__ Bl,
    const float* __restrict__ bias, const float* __restrict__ uvec,
    const float* __restrict__ vvec, int mode, float* __restrict__ out_f,
    __nv_bfloat16* __restrict__ o1h, __nv_bfloat16* __restrict__ o1l,
    __nv_bfloat16* __restrict__ o2h, __nv_bfloat16* __restrict__ o2l)
{
    extern __shared__ __align__(16) char smem[];
    const uint32_t sb0 = smem_u32(smem);
    const int tid = threadIdx.x, lane = tid & 31, w = tid >> 5;
    const int wm = w >> 2, wn = w & 3;
    const int m0 = blockIdx.x * 128, n0 = blockIdx.y * 128;

    float acc[4][4][4];
#pragma unroll
    for (int i = 0; i < 4; i++)
#pragma unroll
        for (int j = 0; j < 4; j++)
#pragma unroll
            for (int q = 0; q < 4; q++) acc[i][j][q] = 0.f;

    const int NC = DD / 32;
    stage_load(sb0, Ah, Al, Bh, Bl, m0, n0, DD, DD, 0, tid);
    cp_commit();
    for (int c = 0; c < NC; c++) {
        if (c + 1 < NC) {
            stage_load(sb0 + ((c + 1) & 1) * STAGE_SZ, Ah, Al, Bh, Bl,
                       m0, n0, DD, DD, (c + 1) * 32, tid);
            cp_commit();
            asm volatile("cp.async.wait_group 1;");
        } else {
            asm volatile("cp.async.wait_group 0;");
        }
        __syncthreads();
        compute_chunk(sb0 + (c & 1) * STAGE_SZ, wm, wn, lane, acc);
        __syncthreads();
    }

    const int g = lane >> 2, t2 = (lane & 3) * 2;
#pragma unroll
    for (int i = 0; i < 4; i++) {
#pragma unroll
        for (int j = 0; j < 4; j++) {
#pragma unroll
            for (int half = 0; half < 2; half++) {
                const int grow = m0 + wm * 64 + i * 16 + g + half * 8;
                const int gcol = n0 + wn * 32 + j * 8 + t2;
                float v0 = acc[i][j][half * 2 + 0] + bias[gcol];
                float v1 = acc[i][j][half * 2 + 1] + bias[gcol + 1];
                if (mode == 0) {
                    *(float2*)&out_f[(size_t)grow * DD + gcol] = make_float2(v0, v1);
                } else {
                    const int b = grow >> 10, s = grow & 1023;
                    const int h = gcol >> 6, dd = gcol & 63;
                    const size_t base = (((size_t)(b * HHN + h) << 10) + s) * DHD + dd;
                    if (mode == 2) {
                        __nv_bfloat16 h0, l0, h1, l1;
                        split2(v0, h0, l0); split2(v1, h1, l1);
                        *(__nv_bfloat162*)&o1h[base] = __nv_bfloat162(h0, h1);
                        *(__nv_bfloat162*)&o1l[base] = __nv_bfloat162(l0, l1);
                    } else {
                        __nv_bfloat16 h0, l0, h1, l1;
                        split2(v0 + uvec[dd], h0, l0); split2(v1 + uvec[dd + 1], h1, l1);
                        *(__nv_bfloat162*)&o1h[base] = __nv_bfloat162(h0, h1);
                        *(__nv_bfloat162*)&o1l[base] = __nv_bfloat162(l0, l1);
                        split2(v0 + vvec[dd], h0, l0); split2(v1 + vvec[dd + 1], h1, l1);
                        *(__nv_bfloat162*)&o2h[base] = __nv_bfloat162(h0, h1);
                        *(__nv_bfloat162*)&o2l[base] = __nv_bfloat162(l0, l1);
                    }
                }
            }
        }
    }
}

// ================= batched QK^T / QR^T (mma.sync, K=64) =================
__global__ __launch_bounds__(256, 1) void mm_qkt(
    const __nv_bfloat16* __restrict__ quh, const __nv_bfloat16* __restrict__ qul,
    const __nv_bfloat16* __restrict__ qvh, const __nv_bfloat16* __restrict__ qvl,
    const __nv_bfloat16* __restrict__ khh, const __nv_bfloat16* __restrict__ khl,
    const __nv_bfloat16* __restrict__ rhh, const __nv_bfloat16* __restrict__ rhl,
    float* __restrict__ acout, float* __restrict__ tout)
{
    extern __shared__ __align__(16) char smem[];
    const uint32_t sb0 = smem_u32(smem);
    const int tid = threadIdx.x, lane = tid & 31, w = tid >> 5;
    const int wm = w >> 2, wn = w & 3;
    const int bh = blockIdx.z & 63;
    const int which = blockIdx.z >> 6;
    const int m0 = blockIdx.x * 128;
    const int j0 = blockIdx.y * 128;

    const __nv_bfloat16* Ah = (which ? qvh : quh) + (size_t)bh * SSQ * DHD;
    const __nv_bfloat16* Al = (which ? qvl : qul) + (size_t)bh * SSQ * DHD;
    const __nv_bfloat16* Bh = (which ? rhh : khh) + (size_t)bh * SSQ * DHD;
    const __nv_bfloat16* Bl = (which ? rhl : khl) + (size_t)bh * SSQ * DHD;

    float acc[4][4][4];
#pragma unroll
    for (int i = 0; i < 4; i++)
#pragma unroll
        for (int j = 0; j < 4; j++)
#pragma unroll
            for (int q = 0; q < 4; q++) acc[i][j][q] = 0.f;

    stage_load(sb0, Ah, Al, Bh, Bl, j0, m0, DHD, DHD, 0, tid);
    cp_commit();
    for (int c = 0; c < 2; c++) {
        if (c == 0) {
            stage_load(sb0 + STAGE_SZ, Ah, Al, Bh, Bl, j0, m0, DHD, DHD, 32, tid);
            cp_commit();
            asm volatile("cp.async.wait_group 1;");
        } else {
            asm volatile("cp.async.wait_group 0;");
        }
        __syncthreads();
        compute_chunk(sb0 + c * STAGE_SZ, wm, wn, lane, acc);
        __syncthreads();
    }

    float* out = (which ? tout : acout) + (size_t)bh * SSQ * SSQ;
    const int g = lane >> 2, t2 = (lane & 3) * 2;
#pragma unroll
    for (int i = 0; i < 4; i++)
#pragma unroll
        for (int j = 0; j < 4; j++)
#pragma unroll
            for (int half = 0; half < 2; half++) {
                const int grow = j0 + wm * 64 + i * 16 + g + half * 8;
                const int gcol = m0 + wn * 32 + j * 8 + t2;
                *(float2*)&out[(size_t)grow * SSQ + gcol] =
                    make_float2(acc[i][j][half * 2], acc[i][j][half * 2 + 1]);
            }
}

// ================= fused softmax + PV (mma.sync) =================
// smem: WH 0..16K, WL 16K..32K, per-warp P: 32K + w*8K (hi 4K, lo 4K), z at 96K
#define FP_WH 0
#define FP_WL 16384
#define FP_P  32768
#define FP_Z  98304
#define FP_SMEM (FP_Z + 512 + 16)

__global__ __launch_bounds__(256, 2) void fused_pv(
    const float* __restrict__ acin, const float* __restrict__ tin,
    const __nv_bfloat16* __restrict__ wh, const __nv_bfloat16* __restrict__ wl,
    float* __restrict__ oout)
{
    extern __shared__ __align__(16) char smem[];
    const uint32_t sb = smem_u32(smem);
    const int tid = threadIdx.x, lane = tid & 31, w = tid >> 5;
    const int bh = blockIdx.y;
    const int jw = blockIdx.x * 128 + w * 16;

    const uint32_t WHb = sb + FP_WH, WLb = sb + FP_WL;
    const uint32_t PHb = sb + FP_P + w * 8192;
    const uint32_t PLb = PHb + 4096;
    char* phc = smem + FP_P + w * 8192;
    char* plc = phc + 4096;
    float* zsm = (float*)(smem + FP_Z);

    const int pr = lane >> 1;            // 0..15 row within warp tile
    const int j  = jw + pr;
    const int mb = (lane & 1) * 64;
    const float* acrow = acin + ((size_t)bh * SSQ + j) * SSQ;
    const float* trow  = tin  + ((size_t)bh * SSQ + j) * SSQ;
    const __nv_bfloat16* whp = wh + (size_t)bh * SSQ * DHD;
    const __nv_bfloat16* wlp = wl + (size_t)bh * SSQ * DHD;

    float acc[8][4];
#pragma unroll
    for (int n = 0; n < 8; n++)
#pragma unroll
        for (int q = 0; q < 4; q++) acc[n][q] = 0.f;
    float zp = 0.f;

    for (int mt = 0; mt < 8; mt++) {
        const int m0 = mt * 128;
        __syncthreads();
        // load w tile hi/lo (128 x 64 bf16 each), chunk-swizzled for ldmatrix.trans
#pragma unroll
        for (int i = 0; i < 4; i++) {
            int idx = i * 256 + tid;
            int r = idx >> 3, c = idx & 7;
            uint32_t off = r * 128 + ((c ^ (r & 7)) << 4);
            cp16(WHb + off, whp + (size_t)(m0 + r) * DHD + c * 8);
            cp16(WLb + off, wlp + (size_t)(m0 + r) * DHD + c * 8);
        }
        cp_commit();
        asm volatile("cp.async.wait_group 0;");
        __syncthreads();

        // compute P rows: exp((ac+bd)*scale), no max shift (logits bounded)
        const float* ap = acrow + m0 + mb;
#pragma unroll 4
        for (int i = 0; i < 64; i += 2) {
            const int m = m0 + mb + i;
            float s01[2];
#pragma unroll
            for (int e = 0; e < 2; e++) {
                const int dlt = m + e - j;
                float bd;
                if (dlt <= 0)      bd = trow[dlt + 1023];
                else if (dlt == 1) bd = 0.f;
                else               bd = trow[SSQ + dlt - 2];
                s01[e] = __expf((ap[i + e] + bd) * ATT_SCALE);
            }
            zp += s01[0] + s01[1];
            __nv_bfloat16 h0, l0, h1, l1;
            split2(s01[0], h0, l0); split2(s01[1], h1, l1);
            const int mm = mb + i;
            const int ch = mm >> 3;
            const uint32_t off = pr * 256 + ((ch ^ (pr & 7)) << 4) + (mm & 7) * 2;
            *(__nv_bfloat162*)(phc + off) = __nv_bfloat162(h0, h1);
            *(__nv_bfloat162*)(plc + off) = __nv_bfloat162(l0, l1);
        }
        __syncwarp();

        // mma: O += P * w  (3 split passes)
#pragma unroll
        for (int ks = 0; ks < 8; ks++) {
            uint32_t aph[4], apl[4];
            {
                const int row = lane & 15;
                const int ch = ks * 2 + (lane >> 4);
                const uint32_t off = row * 256 + ((ch ^ (row & 7)) << 4);
                ldsm4(aph[0], aph[1], aph[2], aph[3], PHb + off);
                ldsm4(apl[0], apl[1], apl[2], apl[3], PLb + off);
            }
#pragma unroll
            for (int g2 = 0; g2 < 4; g2++) {
                const int k = ks * 16 + ((lane >> 3) & 1) * 8 + (lane & 7);
                const int nc = g2 * 2 + (lane >> 4);
                const uint32_t off = k * 128 + ((nc ^ (k & 7)) << 4);
                uint32_t h0, h1, h2, h3, l0, l1, l2, l3;
                ldsm4t(h0, h1, h2, h3, WHb + off);
                ldsm4t(l0, l1, l2, l3, WLb + off);
                uint32_t B0[2] = {h0, h1}, B1[2] = {h2, h3};
                uint32_t C0[2] = {l0, l1}, C1[2] = {l2, l3};
                mma_bf16(acc[2*g2],     aph, B0);
                mma_bf16(acc[2*g2],     apl, B0);
                mma_bf16(acc[2*g2],     aph, C0);
                mma_bf16(acc[2*g2 + 1], aph, B1);
                mma_bf16(acc[2*g2 + 1], apl, B1);
                mma_bf16(acc[2*g2 + 1], aph, C1);
            }
        }
    }

    // z per row -> smem
    float zt = zp + __shfl_xor_sync(0xffffffffu, zp, 1);
    if ((lane & 1) == 0) zsm[w * 16 + pr] = zt;
    __syncwarp();

    const int orow = lane >> 2;
    const float inv0 = 1.f / zsm[w * 16 + orow];
    const float inv1 = 1.f / zsm[w * 16 + orow + 8];
    const int b = bh >> 4, h = bh & 15;
    const size_t rb0 = ((size_t)(b << 10) + jw + orow) << 10;
    const size_t rb1 = ((size_t)(b << 10) + jw + orow + 8) << 10;
#pragma unroll
    for (int ng = 0; ng < 8; ng++) {
        const int d = h * 64 + ng * 8 + (lane & 3) * 2;
        *(float2*)&oout[rb0 + d] = make_float2(acc[ng][0] * inv0, acc[ng][1] * inv0);
        *(float2*)&oout[rb1 + d] = make_float2(acc[ng][2] * inv1, acc[ng][3] * inv1);
    }
}

// =====================================================================
extern "C" void kernel_launch(void* const* d_in, const int* in_sizes, int n_in,
                              void* d_out, int out_size)
{
    const float* x   = (const float*)d_in[0];
    const float* u   = (const float*)d_in[1];
    const float* v   = (const float*)d_in[2];
    const float* pos = (const float*)d_in[3];
    const float* Wq  = (const float*)d_in[4];
    const float* bq  = (const float*)d_in[5];
    const float* Wk  = (const float*)d_in[6];
    const float* bk  = (const float*)d_in[7];
    const float* Wv  = (const float*)d_in[8];
    const float* bv  = (const float*)d_in[9];
    const float* Wc  = (const float*)d_in[10];
    const float* bc  = (const float*)d_in[11];
    float* out = (float*)d_out;

    float *tb, *ac, *ob;
    __nv_bfloat16* bf;
    cudaGetSymbolAddress((void**)&tb,  g_t);
    cudaGetSymbolAddress((void**)&ac,  g_ac);
    cudaGetSymbolAddress((void**)&ob,  g_o);
    cudaGetSymbolAddress((void**)&bf,  g_bf);

    cudaFuncSetAttribute(mm_gemm, cudaFuncAttributeMaxDynamicSharedMemorySize, SMEM_BYTES);
    cudaFuncSetAttribute(mm_qkt,  cudaFuncAttributeMaxDynamicSharedMemorySize, SMEM_BYTES);
    cudaFuncSetAttribute(fused_pv, cudaFuncAttributeMaxDynamicSharedMemorySize, FP_SMEM);

    conv_split<<<(int)((NX + 255) / 256), 256>>>(x,  bf + O_XH,  bf + O_XL,  (int)NX);
    conv_split<<<(int)((NW + 255) / 256), 256>>>(Wq, bf + O_WQH, bf + O_WQL, (int)NW);
    conv_split<<<(int)((NW + 255) / 256), 256>>>(Wk, bf + O_WKH, bf + O_WKL, (int)NW);
    conv_split<<<(int)((NW + 255) / 256), 256>>>(Wv, bf + O_WVH, bf + O_WVL, (int)NW);
    conv_split<<<(int)((NW + 255) / 256), 256>>>(Wc, bf + O_WCH, bf + O_WCL, (int)NW);
    conv_pos  <<<(int)((NH + 255) / 256), 256>>>(pos, bf + O_RHH, bf + O_RHL);

    dim3 gp(32, 8);
    mm_gemm<<<gp, 256, SMEM_BYTES>>>(bf + O_XH, bf + O_XL, bf + O_WQH, bf + O_WQL,
        bq, u, v, 1, nullptr,
        bf + O_QUH, bf + O_QUL, bf + O_QVH, bf + O_QVL);
    mm_gemm<<<gp, 256, SMEM_BYTES>>>(bf + O_XH, bf + O_XL, bf + O_WKH, bf + O_WKL,
        bk, u, v, 2, nullptr,
        bf + O_KHH, bf + O_KHL, nullptr, nullptr);
    mm_gemm<<<gp, 256, SMEM_BYTES>>>(bf + O_XH, bf + O_XL, bf + O_WVH, bf + O_WVL,
        bv, u, v, 2, nullptr,
        bf + O_VWH, bf + O_VWL, nullptr, nullptr);

    mm_qkt<<<dim3(8, 8, 128), 256, SMEM_BYTES>>>(
        bf + O_QUH, bf + O_QUL, bf + O_QVH, bf + O_QVL,
        bf + O_KHH, bf + O_KHL, bf + O_RHH, bf + O_RHL, ac, tb);

    fused_pv<<<dim3(8, 64), 256, FP_SMEM>>>(ac, tb, bf + O_VWH, bf + O_VWL, ob);

    conv_split<<<(int)((NX + 255) / 256), 256>>>(ob, bf + O_OBH, bf + O_OBL, (int)NX);
    mm_gemm<<<gp, 256, SMEM_BYTES>>>(bf + O_OBH, bf + O_OBL, bf + O_WCH, bf + O_WCL,
        bc, u, v, 0, out, nullptr, nullptr, nullptr, nullptr);
}

// round 5
// speedup vs baseline: 1.9336x; 1.9336x over previous
#include <cuda_runtime.h>
#include <cuda_bf16.h>
#include <cstdint>
#include <math.h>

#define SSQ  1024
#define DD   1024
#define HHN  16
#define DHD  64
#define BHN  64
#define MTOT 4096
#define ATT_SCALE 0.03125f

// ---------------- fp32 scratch ----------------
__device__ float g_t [(size_t)BHN * SSQ * SSQ];   // 256 MB
__device__ float g_ac[(size_t)BHN * SSQ * SSQ];   // 256 MB

// ---------------- bf16 pool ----------------
#define NX   ((size_t)MTOT * DD)
#define NW   ((size_t)DD * DD)
#define NH   ((size_t)BHN * SSQ * DHD)
#define O_XH  ((size_t)0)
#define O_XL  (O_XH + NX)
#define O_WQH (O_XL + NX)
#define O_WQL (O_WQH + NW)
#define O_WKH (O_WQL + NW)
#define O_WKL (O_WKH + NW)
#define O_WVH (O_WKL + NW)
#define O_WVL (O_WVH + NW)
#define O_WCH (O_WVL + NW)
#define O_WCL (O_WCH + NW)
#define O_QUH (O_WCL + NW)
#define O_QUL (O_QUH + NH)
#define O_QVH (O_QUL + NH)
#define O_QVL (O_QVH + NH)
#define O_KHH (O_QVL + NH)
#define O_KHL (O_KHH + NH)
#define O_RHH (O_KHL + NH)
#define O_RHL (O_RHH + NH)
#define O_VWH (O_RHL + NH)
#define O_VWL (O_VWH + NH)
#define O_OBH (O_VWL + NH)
#define O_OBL (O_OBH + NX)
#define BF_TOTAL (O_OBL + NX)
__device__ __align__(16) __nv_bfloat16 g_bf[BF_TOTAL];

// ================= helpers =================
__device__ __forceinline__ uint32_t smem_u32(const void* p) {
    uint32_t a;
    asm("{ .reg .u64 t; cvta.to.shared.u64 t, %1; cvt.u32.u64 %0, t; }" : "=r"(a) : "l"(p));
    return a;
}
__device__ __forceinline__ void split2(float v, __nv_bfloat16& h, __nv_bfloat16& l) {
    h = __float2bfloat16(v);
    l = __float2bfloat16(v - __bfloat162float(h));
}
__device__ __forceinline__ void cp16(uint32_t dst, const void* src) {
    asm volatile("cp.async.cg.shared.global [%0], [%1], 16;" :: "r"(dst), "l"(src));
}
__device__ __forceinline__ void cp_commit() { asm volatile("cp.async.commit_group;"); }
__device__ __forceinline__ void ldsm4(uint32_t& r0, uint32_t& r1, uint32_t& r2, uint32_t& r3,
                                      uint32_t addr) {
    asm volatile("ldmatrix.sync.aligned.m8n8.x4.shared.b16 {%0,%1,%2,%3}, [%4];"
                 : "=r"(r0), "=r"(r1), "=r"(r2), "=r"(r3) : "r"(addr));
}
__device__ __forceinline__ void ldsm4t(uint32_t& r0, uint32_t& r1, uint32_t& r2, uint32_t& r3,
                                       uint32_t addr) {
    asm volatile("ldmatrix.sync.aligned.m8n8.x4.trans.shared.b16 {%0,%1,%2,%3}, [%4];"
                 : "=r"(r0), "=r"(r1), "=r"(r2), "=r"(r3) : "r"(addr));
}
__device__ __forceinline__ void mma_bf16(float* d, const uint32_t* a, const uint32_t* b) {
    asm volatile(
        "mma.sync.aligned.m16n8k16.row.col.f32.bf16.bf16.f32 "
        "{%0,%1,%2,%3}, {%4,%5,%6,%7}, {%8,%9}, {%0,%1,%2,%3};"
        : "+f"(d[0]), "+f"(d[1]), "+f"(d[2]), "+f"(d[3])
        : "r"(a[0]), "r"(a[1]), "r"(a[2]), "r"(a[3]), "r"(b[0]), "r"(b[1]));
}
__device__ __forceinline__ uint32_t swadr(uint32_t tb, int r, int c) {
    return tb + r * 64 + (((c ^ ((r >> 1) & 3))) << 4);
}

#define STAGE_SZ 32768
#define SMEM_BYTES (2 * STAGE_SZ)

__device__ __forceinline__ void stage_load(
    uint32_t sb, const __nv_bfloat16* Ah, const __nv_bfloat16* Al,
    const __nv_bfloat16* Bh, const __nv_bfloat16* Bl,
    int arow0, int brow0, int ldA, int ldB, int k0, int tid)
{
#pragma unroll
    for (int half = 0; half < 2; half++) {
        const int q = half * 256 + tid;
        const int r = q >> 2, c = q & 3;
        const int kel = k0 + c * 8;
        cp16(swadr(sb,          r, c), Ah + (size_t)(arow0 + r) * ldA + kel);
        cp16(swadr(sb +  8192,  r, c), Al + (size_t)(arow0 + r) * ldA + kel);
        cp16(swadr(sb + 16384,  r, c), Bh + (size_t)(brow0 + r) * ldB + kel);
        cp16(swadr(sb + 24576,  r, c), Bl + (size_t)(brow0 + r) * ldB + kel);
    }
}

__device__ __forceinline__ void compute_chunk(uint32_t sb, int wm, int wn, int lane,
                                              float acc[4][4][4])
{
    const uint32_t Ahb = sb, Alb = sb + 8192, Bhb = sb + 16384, Blb = sb + 24576;
#pragma unroll
    for (int kk = 0; kk < 2; kk++) {
        uint32_t ah[4][4], al[4][4], bh[4][2], bl[4][2];
        const int ar = wm * 64 + (lane & 15);
        const int ac = 2 * kk + (lane >> 4);
#pragma unroll
        for (int i = 0; i < 4; i++) {
            ldsm4(ah[i][0], ah[i][1], ah[i][2], ah[i][3], swadr(Ahb, ar + i * 16, ac));
            ldsm4(al[i][0], al[i][1], al[i][2], al[i][3], swadr(Alb, ar + i * 16, ac));
        }
        const int br = wn * 32 + (lane & 7) + ((lane >> 4) << 3);
        const int bc = 2 * kk + ((lane >> 3) & 1);
#pragma unroll
        for (int p = 0; p < 2; p++) {
            uint32_t t0, t1, t2, t3;
            ldsm4(t0, t1, t2, t3, swadr(Bhb, br + p * 16, bc));
            bh[2*p][0] = t0; bh[2*p][1] = t1; bh[2*p+1][0] = t2; bh[2*p+1][1] = t3;
            ldsm4(t0, t1, t2, t3, swadr(Blb, br + p * 16, bc));
            bl[2*p][0] = t0; bl[2*p][1] = t1; bl[2*p+1][0] = t2; bl[2*p+1][1] = t3;
        }
#pragma unroll
        for (int i = 0; i < 4; i++)
#pragma unroll
            for (int j = 0; j < 4; j++) {
                mma_bf16(acc[i][j], ah[i], bh[j]);
                mma_bf16(acc[i][j], ah[i], bl[j]);
                mma_bf16(acc[i][j], al[i], bh[j]);
            }
    }
}

// ================= conversion kernels =================
__global__ __launch_bounds__(256) void conv_split(
    const float* __restrict__ s, __nv_bfloat16* __restrict__ h,
    __nv_bfloat16* __restrict__ l, int n)
{
    int i = blockIdx.x * 256 + threadIdx.x;
    if (i < n) {
        __nv_bfloat16 hh, ll; split2(s[i], hh, ll);
        h[i] = hh; l[i] = ll;
    }
}

__global__ __launch_bounds__(256) void conv_pos(
    const float* __restrict__ pos, __nv_bfloat16* __restrict__ h,
    __nv_bfloat16* __restrict__ l)
{
    int d = blockIdx.x * 256 + threadIdx.x;
    int bh = d >> 16;
    int s  = (d >> 6) & 1023;
    int dd = d & 63;
    int b = bh >> 4, hh_ = bh & 15;
    float v = pos[(((size_t)b << 10) + s) * 1024 + (hh_ << 6) + dd];
    __nv_bfloat16 hb, lb; split2(v, hb, lb);
    h[d] = hb; l[d] = lb;
}

// ================= projection GEMM (mma.sync) =================
__global__ __launch_bounds__(256, 1) void mm_gemm(
    const __nv_bfloat16* __restrict__ Ah, const __nv_bfloat16* __restrict__ Al,
    const __nv_bfloat16* __restrict__ Bh, const __nv_bfloat16* __restrict__ Bl,
    const float* __restrict__ bias, const float* __restrict__ uvec,
    const float* __restrict__ vvec, int mode, float* __restrict__ out_f,
    __nv_bfloat16* __restrict__ o1h, __nv_bfloat16* __restrict__ o1l,
    __nv_bfloat16* __restrict__ o2h, __nv_bfloat16* __restrict__ o2l)
{
    extern __shared__ __align__(16) char smem[];
    const uint32_t sb0 = smem_u32(smem);
    const int tid = threadIdx.x, lane = tid & 31, w = tid >> 5;
    const int wm = w >> 2, wn = w & 3;
    const int m0 = blockIdx.x * 128, n0 = blockIdx.y * 128;

    float acc[4][4][4];
#pragma unroll
    for (int i = 0; i < 4; i++)
#pragma unroll
        for (int j = 0; j < 4; j++)
#pragma unroll
            for (int q = 0; q < 4; q++) acc[i][j][q] = 0.f;

    const int NC = DD / 32;
    stage_load(sb0, Ah, Al, Bh, Bl, m0, n0, DD, DD, 0, tid);
    cp_commit();
    for (int c = 0; c < NC; c++) {
        if (c + 1 < NC) {
            stage_load(sb0 + ((c + 1) & 1) * STAGE_SZ, Ah, Al, Bh, Bl,
                       m0, n0, DD, DD, (c + 1) * 32, tid);
            cp_commit();
            asm volatile("cp.async.wait_group 1;");
        } else {
            asm volatile("cp.async.wait_group 0;");
        }
        __syncthreads();
        compute_chunk(sb0 + (c & 1) * STAGE_SZ, wm, wn, lane, acc);
        __syncthreads();
    }

    const int g = lane >> 2, t2 = (lane & 3) * 2;
#pragma unroll
    for (int i = 0; i < 4; i++) {
#pragma unroll
        for (int j = 0; j < 4; j++) {
#pragma unroll
            for (int half = 0; half < 2; half++) {
                const int grow = m0 + wm * 64 + i * 16 + g + half * 8;
                const int gcol = n0 + wn * 32 + j * 8 + t2;
                float v0 = acc[i][j][half * 2 + 0] + bias[gcol];
                float v1 = acc[i][j][half * 2 + 1] + bias[gcol + 1];
                if (mode == 0) {
                    *(float2*)&out_f[(size_t)grow * DD + gcol] = make_float2(v0, v1);
                } else {
                    const int b = grow >> 10, s = grow & 1023;
                    const int h = gcol >> 6, dd = gcol & 63;
                    const size_t base = (((size_t)(b * HHN + h) << 10) + s) * DHD + dd;
                    if (mode == 2) {
                        __nv_bfloat16 h0, l0, h1, l1;
                        split2(v0, h0, l0); split2(v1, h1, l1);
                        *(__nv_bfloat162*)&o1h[base] = __nv_bfloat162(h0, h1);
                        *(__nv_bfloat162*)&o1l[base] = __nv_bfloat162(l0, l1);
                    } else {
                        __nv_bfloat16 h0, l0, h1, l1;
                        split2(v0 + uvec[dd], h0, l0); split2(v1 + uvec[dd + 1], h1, l1);
                        *(__nv_bfloat162*)&o1h[base] = __nv_bfloat162(h0, h1);
                        *(__nv_bfloat162*)&o1l[base] = __nv_bfloat162(l0, l1);
                        split2(v0 + vvec[dd], h0, l0); split2(v1 + vvec[dd + 1], h1, l1);
                        *(__nv_bfloat162*)&o2h[base] = __nv_bfloat162(h0, h1);
                        *(__nv_bfloat162*)&o2l[base] = __nv_bfloat162(l0, l1);
                    }
                }
            }
        }
    }
}

// ================= batched QK^T / QR^T (mma.sync, K=64) =================
__global__ __launch_bounds__(256, 1) void mm_qkt(
    const __nv_bfloat16* __restrict__ quh, const __nv_bfloat16* __restrict__ qul,
    const __nv_bfloat16* __restrict__ qvh, const __nv_bfloat16* __restrict__ qvl,
    const __nv_bfloat16* __restrict__ khh, const __nv_bfloat16* __restrict__ khl,
    const __nv_bfloat16* __restrict__ rhh, const __nv_bfloat16* __restrict__ rhl,
    float* __restrict__ acout, float* __restrict__ tout)
{
    extern __shared__ __align__(16) char smem[];
    const uint32_t sb0 = smem_u32(smem);
    const int tid = threadIdx.x, lane = tid & 31, w = tid >> 5;
    const int wm = w >> 2, wn = w & 3;
    const int bh = blockIdx.z & 63;
    const int which = blockIdx.z >> 6;
    const int m0 = blockIdx.x * 128;
    const int j0 = blockIdx.y * 128;

    const __nv_bfloat16* Ah = (which ? qvh : quh) + (size_t)bh * SSQ * DHD;
    const __nv_bfloat16* Al = (which ? qvl : qul) + (size_t)bh * SSQ * DHD;
    const __nv_bfloat16* Bh = (which ? rhh : khh) + (size_t)bh * SSQ * DHD;
    const __nv_bfloat16* Bl = (which ? rhl : khl) + (size_t)bh * SSQ * DHD;

    float acc[4][4][4];
#pragma unroll
    for (int i = 0; i < 4; i++)
#pragma unroll
        for (int j = 0; j < 4; j++)
#pragma unroll
            for (int q = 0; q < 4; q++) acc[i][j][q] = 0.f;

    stage_load(sb0, Ah, Al, Bh, Bl, j0, m0, DHD, DHD, 0, tid);
    cp_commit();
    for (int c = 0; c < 2; c++) {
        if (c == 0) {
            stage_load(sb0 + STAGE_SZ, Ah, Al, Bh, Bl, j0, m0, DHD, DHD, 32, tid);
            cp_commit();
            asm volatile("cp.async.wait_group 1;");
        } else {
            asm volatile("cp.async.wait_group 0;");
        }
        __syncthreads();
        compute_chunk(sb0 + c * STAGE_SZ, wm, wn, lane, acc);
        __syncthreads();
    }

    float* out = (which ? tout : acout) + (size_t)bh * SSQ * SSQ;
    const int g = lane >> 2, t2 = (lane & 3) * 2;
#pragma unroll
    for (int i = 0; i < 4; i++)
#pragma unroll
        for (int j = 0; j < 4; j++)
#pragma unroll
            for (int half = 0; half < 2; half++) {
                const int grow = j0 + wm * 64 + i * 16 + g + half * 8;
                const int gcol = m0 + wn * 32 + j * 8 + t2;
                *(float2*)&out[(size_t)grow * SSQ + gcol] =
                    make_float2(acc[i][j][half * 2], acc[i][j][half * 2 + 1]);
            }
}

// ================= fused softmax + PV (mma.sync) =================
// smem: WH 0..16K, WL 16K..32K, per-warp P: 32K + w*8K (hi 4K, lo 4K), z at 96K
#define FP_WH 0
#define FP_WL 16384
#define FP_P  32768
#define FP_Z  98304
#define FP_SMEM (FP_Z + 512 + 16)

__global__ __launch_bounds__(256, 2) void fused_pv(
    const float* __restrict__ acin, const float* __restrict__ tin,
    const __nv_bfloat16* __restrict__ wh, const __nv_bfloat16* __restrict__ wl,
    __nv_bfloat16* __restrict__ obh, __nv_bfloat16* __restrict__ obl)
{
    extern __shared__ __align__(16) char smem[];
    const uint32_t sb = smem_u32(smem);
    const int tid = threadIdx.x, lane = tid & 31, w = tid >> 5;
    const int bh = blockIdx.y;
    const int jw = blockIdx.x * 128 + w * 16;

    const uint32_t WHb = sb + FP_WH, WLb = sb + FP_WL;
    const uint32_t PHb = sb + FP_P + w * 8192;
    const uint32_t PLb = PHb + 4096;
    char* phc = smem + FP_P + w * 8192;
    char* plc = phc + 4096;
    float* zsm = (float*)(smem + FP_Z);

    const __nv_bfloat16* whp = wh + (size_t)bh * SSQ * DHD;
    const __nv_bfloat16* wlp = wl + (size_t)bh * SSQ * DHD;
    const float* acbase = acin + ((size_t)bh * SSQ + jw) * SSQ;
    const float* tbase  = tin  + ((size_t)bh * SSQ + jw) * SSQ;

    float acc[8][4];
#pragma unroll
    for (int n = 0; n < 8; n++)
#pragma unroll
        for (int q = 0; q < 4; q++) acc[n][q] = 0.f;
    float zacc[16];
#pragma unroll
    for (int r = 0; r < 16; r++) zacc[r] = 0.f;

    for (int mt = 0; mt < 8; mt++) {
        const int m0 = mt * 128;
        __syncthreads();
        // load w tile hi/lo (128 x 64 bf16 each), chunk-swizzled for ldmatrix.trans
#pragma unroll
        for (int i = 0; i < 4; i++) {
            int idx = i * 256 + tid;
            int r = idx >> 3, c = idx & 7;
            uint32_t off = r * 128 + ((c ^ (r & 7)) << 4);
            cp16(WHb + off, whp + (size_t)(m0 + r) * DHD + c * 8);
            cp16(WLb + off, wlp + (size_t)(m0 + r) * DHD + c * 8);
        }
        cp_commit();
        asm volatile("cp.async.wait_group 0;");
        __syncthreads();

        // P phase: warp-cooperative, coalesced. Row r: lanes cover columns.
#pragma unroll
        for (int r = 0; r < 16; r++) {
            const int j = jw + r;
            const float* acrow = acbase + (size_t)r * SSQ + m0;
            const float* trow  = tbase  + (size_t)r * SSQ;
#pragma unroll
            for (int half = 0; half < 2; half++) {
                const int mm = half * 64 + 2 * lane;      // even col in [0,128)
                const int m = m0 + mm;
                const float2 a2 = *(const float2*)(acrow + mm);
                float s0, s1;
                {
                    const int dlt = m - j;
                    const int idx = dlt + ((dlt <= 0) ? 1023 : 1022);
                    float bd = trow[idx];
                    if (dlt == 1) bd = 0.f;
                    s0 = __expf((a2.x + bd) * ATT_SCALE);
                }
                {
                    const int dlt = m + 1 - j;
                    const int idx = dlt + ((dlt <= 0) ? 1023 : 1022);
                    float bd = trow[idx];
                    if (dlt == 1) bd = 0.f;
                    s1 = __expf((a2.y + bd) * ATT_SCALE);
                }
                zacc[r] += s0 + s1;
                __nv_bfloat16 h0, l0, h1, l1;
                split2(s0, h0, l0); split2(s1, h1, l1);
                const int ch = mm >> 3;
                const uint32_t off = r * 256 + ((ch ^ (r & 7)) << 4) + (mm & 7) * 2;
                *(__nv_bfloat162*)(phc + off) = __nv_bfloat162(h0, h1);
                *(__nv_bfloat162*)(plc + off) = __nv_bfloat162(l0, l1);
            }
        }
        __syncwarp();

        // mma: O += P * w  (3 split passes)
#pragma unroll
        for (int ks = 0; ks < 8; ks++) {
            uint32_t aph[4], apl[4];
            {
                const int row = lane & 15;
                const int ch = ks * 2 + (lane >> 4);
                const uint32_t off = row * 256 + ((ch ^ (row & 7)) << 4);
                ldsm4(aph[0], aph[1], aph[2], aph[3], PHb + off);
                ldsm4(apl[0], apl[1], apl[2], apl[3], PLb + off);
            }
#pragma unroll
            for (int g2 = 0; g2 < 4; g2++) {
                const int k = ks * 16 + ((lane >> 3) & 1) * 8 + (lane & 7);
                const int nc = g2 * 2 + (lane >> 4);
                const uint32_t off = k * 128 + ((nc ^ (k & 7)) << 4);
                uint32_t h0, h1, h2, h3, l0, l1, l2, l3;
                ldsm4t(h0, h1, h2, h3, WHb + off);
                ldsm4t(l0, l1, l2, l3, WLb + off);
                uint32_t B0[2] = {h0, h1}, B1[2] = {h2, h3};
                uint32_t C0[2] = {l0, l1}, C1[2] = {l2, l3};
                mma_bf16(acc[2*g2],     aph, B0);
                mma_bf16(acc[2*g2],     apl, B0);
                mma_bf16(acc[2*g2],     aph, C0);
                mma_bf16(acc[2*g2 + 1], aph, B1);
                mma_bf16(acc[2*g2 + 1], apl, B1);
                mma_bf16(acc[2*g2 + 1], aph, C1);
            }
        }
        __syncwarp();
    }

    // reduce z per row (independent butterfly chains, pipelined)
#pragma unroll
    for (int r = 0; r < 16; r++) {
#pragma unroll
        for (int o = 16; o > 0; o >>= 1)
            zacc[r] += __shfl_xor_sync(0xffffffffu, zacc[r], o);
    }
    if (lane == 0) {
#pragma unroll
        for (int r = 0; r < 16; r++) zsm[w * 16 + r] = zacc[r];
    }
    __syncwarp();

    const int orow = lane >> 2;
    const float inv0 = 1.f / zsm[w * 16 + orow];
    const float inv1 = 1.f / zsm[w * 16 + orow + 8];
    const int b = bh >> 4, h = bh & 15;
    const size_t rb0 = ((size_t)(b << 10) + jw + orow) << 10;
    const size_t rb1 = ((size_t)(b << 10) + jw + orow + 8) << 10;
#pragma unroll
    for (int ng = 0; ng < 8; ng++) {
        const int d = h * 64 + ng * 8 + (lane & 3) * 2;
        __nv_bfloat16 h0, l0, h1, l1;
        split2(acc[ng][0] * inv0, h0, l0); split2(acc[ng][1] * inv0, h1, l1);
        *(__nv_bfloat162*)&obh[rb0 + d] = __nv_bfloat162(h0, h1);
        *(__nv_bfloat162*)&obl[rb0 + d] = __nv_bfloat162(l0, l1);
        split2(acc[ng][2] * inv1, h0, l0); split2(acc[ng][3] * inv1, h1, l1);
        *(__nv_bfloat162*)&obh[rb1 + d] = __nv_bfloat162(h0, h1);
        *(__nv_bfloat162*)&obl[rb1 + d] = __nv_bfloat162(l0, l1);
    }
}

// =====================================================================
extern "C" void kernel_launch(void* const* d_in, const int* in_sizes, int n_in,
                              void* d_out, int out_size)
{
    const float* x   = (const float*)d_in[0];
    const float* u   = (const float*)d_in[1];
    const float* v   = (const float*)d_in[2];
    const float* pos = (const float*)d_in[3];
    const float* Wq  = (const float*)d_in[4];
    const float* bq  = (const float*)d_in[5];
    const float* Wk  = (const float*)d_in[6];
    const float* bk  = (const float*)d_in[7];
    const float* Wv  = (const float*)d_in[8];
    const float* bv  = (const float*)d_in[9];
    const float* Wc  = (const float*)d_in[10];
    const float* bc  = (const float*)d_in[11];
    float* out = (float*)d_out;

    float *tb, *ac;
    __nv_bfloat16* bf;
    cudaGetSymbolAddress((void**)&tb,  g_t);
    cudaGetSymbolAddress((void**)&ac,  g_ac);
    cudaGetSymbolAddress((void**)&bf,  g_bf);

    cudaFuncSetAttribute(mm_gemm, cudaFuncAttributeMaxDynamicSharedMemorySize, SMEM_BYTES);
    cudaFuncSetAttribute(mm_qkt,  cudaFuncAttributeMaxDynamicSharedMemorySize, SMEM_BYTES);
    cudaFuncSetAttribute(fused_pv, cudaFuncAttributeMaxDynamicSharedMemorySize, FP_SMEM);

    conv_split<<<(int)((NX + 255) / 256), 256>>>(x,  bf + O_XH,  bf + O_XL,  (int)NX);
    conv_split<<<(int)((NW + 255) / 256), 256>>>(Wq, bf + O_WQH, bf + O_WQL, (int)NW);
    conv_split<<<(int)((NW + 255) / 256), 256>>>(Wk, bf + O_WKH, bf + O_WKL, (int)NW);
    conv_split<<<(int)((NW + 255) / 256), 256>>>(Wv, bf + O_WVH, bf + O_WVL, (int)NW);
    conv_split<<<(int)((NW + 255) / 256), 256>>>(Wc, bf + O_WCH, bf + O_WCL, (int)NW);
    conv_pos  <<<(int)((NH + 255) / 256), 256>>>(pos, bf + O_RHH, bf + O_RHL);

    dim3 gp(32, 8);
    mm_gemm<<<gp, 256, SMEM_BYTES>>>(bf + O_XH, bf + O_XL, bf + O_WQH, bf + O_WQL,
        bq, u, v, 1, nullptr,
        bf + O_QUH, bf + O_QUL, bf + O_QVH, bf + O_QVL);
    mm_gemm<<<gp, 256, SMEM_BYTES>>>(bf + O_XH, bf + O_XL, bf + O_WKH, bf + O_WKL,
        bk, u, v, 2, nullptr,
        bf + O_KHH, bf + O_KHL, nullptr, nullptr);
    mm_gemm<<<gp, 256, SMEM_BYTES>>>(bf + O_XH, bf + O_XL, bf + O_WVH, bf + O_WVL,
        bv, u, v, 2, nullptr,
        bf + O_VWH, bf + O_VWL, nullptr, nullptr);

    mm_qkt<<<dim3(8, 8, 128), 256, SMEM_BYTES>>>(
        bf + O_QUH, bf + O_QUL, bf + O_QVH, bf + O_QVL,
        bf + O_KHH, bf + O_KHL, bf + O_RHH, bf + O_RHL, ac, tb);

    fused_pv<<<dim3(8, 64), 256, FP_SMEM>>>(ac, tb, bf + O_VWH, bf + O_VWL,
                                            bf + O_OBH, bf + O_OBL);

    mm_gemm<<<gp, 256, SMEM_BYTES>>>(bf + O_OBH, bf + O_OBL, bf + O_WCH, bf + O_WCL,
        bc, u, v, 0, out, nullptr, nullptr, nullptr, nullptr);
}